// round 7
// baseline (speedup 1.0000x reference)
#include <cuda_runtime.h>
#include <cuda_bf16.h>
#include <math.h>
#include <stdint.h>

#define B_ROWS 32768
#define OBS    512
#define H1D    1024
#define H2D    1024
#define ACT    64
#define NOUT   (2*ACT)

#define C0_SCALE 134217728.0f      // 2^27: obs*F0 pre-scale into e4m3 range
#define C1_SCALE 65536.0f          // 2^16: hidden-activation pre-scale

// ---------------- device scratch (static: no allocations allowed) ----------------
__device__ uint8_t g_W1f[H1D*OBS];     // e4m3 integer-valued weights
__device__ uint8_t g_W2f[H2D*H1D];
__device__ uint8_t g_W3f[NOUT*H2D];
__device__ float g_b1q[H1D];
__device__ float g_b2q[H2D];
__device__ float g_b3q[NOUT];
__device__ float g_escale[3];          // epilogue scales ws_i / C_{i-1}
__device__ unsigned g_maxbits[3];
__device__ uint8_t g_x[(size_t)B_ROWS*OBS];     // e4m3(obs * F0 * C0)
__device__ uint8_t g_h1[(size_t)B_ROWS*H1D];    // e4m3(relu(.) * C1)
__device__ uint8_t g_h2[(size_t)B_ROWS*H2D];
__device__ float g_net[(size_t)B_ROWS*NOUT];

// ---------------- PTX helpers (sm_103-safe subset only) ----------------
__device__ __forceinline__ uint32_t smem_u32(const void* p) {
    uint32_t a;
    asm("{ .reg .u64 t; cvta.to.shared.u64 t, %1; cvt.u32.u64 %0, t; }" : "=r"(a) : "l"(p));
    return a;
}
__device__ __forceinline__ void cpasync16(uint32_t dst, const void* src) {
    asm volatile("cp.async.cg.shared.global [%0], [%1], 16;" :: "r"(dst), "l"(src));
}
__device__ __forceinline__ void cp_commit() { asm volatile("cp.async.commit_group;" ::: "memory"); }
__device__ __forceinline__ void cp_wait2()  { asm volatile("cp.async.wait_group 2;" ::: "memory"); }
__device__ __forceinline__ void cp_wait1()  { asm volatile("cp.async.wait_group 1;" ::: "memory"); }
__device__ __forceinline__ void cp_wait0()  { asm volatile("cp.async.wait_group 0;" ::: "memory"); }

#define LDSM_X4(r0, r1, r2, r3, addr)                                          \
    asm volatile("ldmatrix.sync.aligned.m8n8.x4.shared.b16 {%0,%1,%2,%3}, [%4];" \
        : "=r"(r0), "=r"(r1), "=r"(r2), "=r"(r3) : "r"(addr))

// fp8 e4m3 MMA: same operand register shape as m16n8k16.bf16 (fragments are the
// b16-pair reinterpretation of the bf16 layout -> identical ldmatrix addressing)
#define MMAFP8(c, a0, a1, a2, a3, b0, b1)                                      \
    asm volatile("mma.sync.aligned.m16n8k32.row.col.f32.e4m3.e4m3.f32 "        \
        "{%0,%1,%2,%3}, {%4,%5,%6,%7}, {%8,%9}, {%0,%1,%2,%3};"                \
        : "+f"((c)[0]), "+f"((c)[1]), "+f"((c)[2]), "+f"((c)[3])               \
        : "r"(a0), "r"(a1), "r"(a2), "r"(a3), "r"(b0), "r"(b1))

// pack two floats -> e4m3x2 (low byte = first arg)
__device__ __forceinline__ uint16_t pack_e4m3(float lo, float hi) {
    uint16_t u;
    asm("cvt.rn.satfinite.e4m3x2.f32 %0, %1, %2;" : "=h"(u) : "f"(hi), "f"(lo));
    return u;
}

// ---------------- quantization prep ----------------
__global__ void zero_max_kernel() {
    if (threadIdx.x < 3) g_maxbits[threadIdx.x] = 0u;
}

// fused 3-tensor max|W|: blocks [0,128)->W1, [128,384)->W2, [384,416)->W3
__global__ void maxabs3_kernel(const float* __restrict__ W1, const float* __restrict__ W2,
                               const float* __restrict__ W3) {
    const float* W; int n, slot, idx, nb;
    int b = blockIdx.x;
    if (b < 128)      { W = W1; n = H1D*OBS;  slot = 0; idx = b;       nb = 128; }
    else if (b < 384) { W = W2; n = H2D*H1D;  slot = 1; idx = b - 128; nb = 256; }
    else              { W = W3; n = NOUT*H2D; slot = 2; idx = b - 384; nb = 32;  }
    unsigned m = 0u;
    for (int i = idx*blockDim.x + threadIdx.x; i < n; i += nb*blockDim.x)
        m = max(m, __float_as_uint(fabsf(W[i])));
    #pragma unroll
    for (int o = 16; o; o >>= 1) m = max(m, __shfl_xor_sync(0xffffffffu, m, o));
    __shared__ unsigned sm[32];
    int lane = threadIdx.x & 31, wid = threadIdx.x >> 5;
    if (lane == 0) sm[wid] = m;
    __syncthreads();
    if (wid == 0) {
        m = (lane < (int)(blockDim.x >> 5)) ? sm[lane] : 0u;
        #pragma unroll
        for (int o = 16; o; o >>= 1) m = max(m, __shfl_xor_sync(0xffffffffu, m, o));
        if (lane == 0) atomicMax(&g_maxbits[slot], m);
    }
}

__device__ __forceinline__ float qwr(float w, float s) {   // integer part only
    float r = rintf(__fdiv_rn(w, s));
    return fminf(fmaxf(r, -127.0f), 127.0f);
}
__device__ __forceinline__ float qb(float b, float s) {
    float r = rintf(__fdiv_rn(b, s));
    r = fminf(fmaxf(r, -128.0f), 127.0f);
    return r * s;
}

__global__ void quant_all_kernel(const float* __restrict__ W1, const float* __restrict__ b1,
                                 const float* __restrict__ W2, const float* __restrict__ b2,
                                 const float* __restrict__ W3, const float* __restrict__ b3,
                                 float s_in) {
    const float ws1 = __fdiv_rn(__uint_as_float(g_maxbits[0]), 127.0f);
    const float ws2 = __fdiv_rn(__uint_as_float(g_maxbits[1]), 127.0f);
    const float ws3 = __fdiv_rn(__uint_as_float(g_maxbits[2]), 127.0f);
    const float sb1 = s_in * ws1;
    const float sb2 = sb1 * ws2;
    const float sb3 = sb2 * ws3;
    const int tid = blockIdx.x*blockDim.x + threadIdx.x;
    const int stride = gridDim.x*blockDim.x;
    if (tid == 0) {
        g_escale[0] = ws1 * (1.0f / C0_SCALE);
        g_escale[1] = ws2 * (1.0f / C1_SCALE);
        g_escale[2] = ws3 * (1.0f / C1_SCALE);
    }
    for (int i = tid; i < H1D*OBS/2; i += stride)
        ((uint16_t*)g_W1f)[i] = pack_e4m3(qwr(W1[2*i], ws1), qwr(W1[2*i+1], ws1));
    for (int i = tid; i < H2D*H1D/2; i += stride)
        ((uint16_t*)g_W2f)[i] = pack_e4m3(qwr(W2[2*i], ws2), qwr(W2[2*i+1], ws2));
    for (int i = tid; i < NOUT*H2D/2; i += stride)
        ((uint16_t*)g_W3f)[i] = pack_e4m3(qwr(W3[2*i], ws3), qwr(W3[2*i+1], ws3));
    for (int i = tid; i < H1D;  i += stride) g_b1q[i] = qb(b1[i], sb1);
    for (int i = tid; i < H2D;  i += stride) g_b2q[i] = qb(b2[i], sb2);
    for (int i = tid; i < NOUT; i += stride) g_b3q[i] = qb(b3[i], sb3);
}

// ---------------- input conversion: e4m3(obs * s_in^2 * C0) ----------------
__global__ void conv_x_kernel(const float* __restrict__ obs) {
    const float F = (float)((1.0/12000.0) * (1.0/12000.0)) * C0_SCALE;
    const size_t n2 = (size_t)B_ROWS * OBS / 2;
    for (size_t i = (size_t)blockIdx.x*blockDim.x + threadIdx.x; i < n2;
         i += (size_t)gridDim.x*blockDim.x) {
        float2 v = ((const float2*)obs)[i];
        ((uint16_t*)g_x)[i] = pack_e4m3(v.x * F, v.y * F);
    }
}

// ---------------- FP8 MMA GEMM ----------------
// D[128,NTILE] per CTA = A[M,K] @ W[N,K]^T (e4m3) ; epilogue: *escale + bias
// (+relu -> e4m3*C1, else fp32). 8 warps 2(M)x4(N); BK=128 fp8 (128B rows, same
// swizzle as bf16 version); 3-stage cp.async ring. Fragment addressing identical
// to the validated bf16 kernel (b16-pair view).
#define BK 128
#define ASTG (128*BK)            // 16 KB A per stage

template<int NTILE, bool RELU>
__global__ __launch_bounds__(256, 1)
void gemm_fp8(const uint8_t* __restrict__ A,
              const uint8_t* __restrict__ Br,  const float* __restrict__ bias,
              int K, int Nd, int sIdx,
              uint8_t* __restrict__ oH, float* __restrict__ oF) {
    constexpr int BSTG = NTILE * BK;            // B bytes per stage
    constexpr int STG  = ASTG + BSTG;
    constexpr int NT   = NTILE / 32;            // n-subtiles per warp (8 or 4)
    extern __shared__ __align__(128) char smem[];
    const uint32_t sb = smem_u32(smem);
    const int tid = threadIdx.x, wid = tid >> 5, lane = tid & 31;
    const int bm = blockIdx.y * 128, bn = blockIdx.x * NTILE;
    const int wm = wid >> 2, wn = wid & 3;

    float acc[4][NT][4];
    #pragma unroll
    for (int i = 0; i < 4; i++)
        #pragma unroll
        for (int j = 0; j < NT; j++)
            #pragma unroll
            for (int v = 0; v < 4; v++) acc[i][j][v] = 0.0f;

    const int nIter = K >> 7;                   // K / 128

    auto load_stage = [&](int i) {
        const uint32_t s0 = sb + (i % 3) * STG;
        const int k0 = i << 7;                  // byte offset along K
        #pragma unroll
        for (int o = 0; o < 4; o++) {           // A: 128 rows x 8 x 16B
            int idx = tid + o * 256;
            int r = idx >> 3, c = idx & 7;
            uint32_t soff = (uint32_t)(r * 128 + ((c ^ (r & 7)) << 4));
            cpasync16(s0 + soff, A + (size_t)(bm + r) * K + k0 + c * 16);
        }
        #pragma unroll
        for (int o = 0; o < NTILE / 32; o++) {  // B: NTILE rows x 8 x 16B
            int idx = tid + o * 256;
            int r = idx >> 3, c = idx & 7;
            cpasync16(s0 + ASTG + (uint32_t)(r * 128 + ((c ^ (r & 7)) << 4)),
                      Br + (size_t)(bn + r) * K + k0 + c * 16);
        }
        cp_commit();
    };

    const int g  = lane >> 3;
    const int glr = lane & 7;
    const int arow = (g & 1) * 8 + glr;
    const int ach  = g >> 1;
    const int brow = (g >> 1) * 8 + glr;
    const int bch  = g & 1;

    load_stage(0);
    if (nIter > 1) load_stage(1);

    for (int i = 0; i < nIter; ++i) {
        if (i + 2 < nIter)      { load_stage(i + 2); cp_wait2(); }
        else if (i + 1 < nIter) { cp_wait1(); }
        else                    { cp_wait0(); }
        __syncthreads();

        const uint32_t s0 = sb + (i % 3) * STG;
        #pragma unroll
        for (int ks = 0; ks < 4; ks++) {        // each ks = 32 fp8 = 2 x 16B chunks
            const int c0 = ks * 2;
            uint32_t bf[NT][2];
            #pragma unroll
            for (int nt2 = 0; nt2 < NT / 2; nt2++) {
                int row = wn * (NTILE / 4) + nt2 * 16 + brow;
                uint32_t addr = s0 + ASTG + row * 128 + (((c0 + bch) ^ (row & 7)) << 4);
                LDSM_X4(bf[2*nt2][0], bf[2*nt2][1], bf[2*nt2+1][0], bf[2*nt2+1][1], addr);
            }
            uint32_t af[4][4];
            #pragma unroll
            for (int mt = 0; mt < 4; mt++) {
                int row = wm * 64 + mt * 16 + arow;
                uint32_t addr = s0 + row * 128 + (((c0 + ach) ^ (row & 7)) << 4);
                LDSM_X4(af[mt][0], af[mt][1], af[mt][2], af[mt][3], addr);
            }
            #pragma unroll
            for (int mt = 0; mt < 4; mt++)
                #pragma unroll
                for (int nt = 0; nt < NT; nt++)
                    MMAFP8(acc[mt][nt], af[mt][0], af[mt][1], af[mt][2], af[mt][3],
                           bf[nt][0], bf[nt][1]);
        }
        __syncthreads();
    }

    // ---- epilogue ----
    const float es = g_escale[sIdx];
    const int qr = lane >> 2;
    const int qc = (lane & 3) * 2;
    #pragma unroll
    for (int mt = 0; mt < 4; mt++) {
        #pragma unroll
        for (int nt = 0; nt < NT; nt++) {
            int col = bn + wn * (NTILE / 4) + nt * 8 + qc;
            float bs0 = __ldg(&bias[col]), bs1 = __ldg(&bias[col + 1]);
            #pragma unroll
            for (int h = 0; h < 2; h++) {
                size_t row = (size_t)(bm + wm * 64 + mt * 16 + qr + h * 8);
                float o0 = fmaf(acc[mt][nt][2*h + 0], es, bs0);
                float o1 = fmaf(acc[mt][nt][2*h + 1], es, bs1);
                if (RELU) {
                    o0 = fmaxf(o0, 0.0f) * C1_SCALE;
                    o1 = fmaxf(o1, 0.0f) * C1_SCALE;
                    *reinterpret_cast<uint16_t*>(oH + row * Nd + col) = pack_e4m3(o0, o1);
                } else {
                    float2 fo; fo.x = o0; fo.y = o1;
                    *reinterpret_cast<float2*>(oF + row * Nd + col) = fo;
                }
            }
        }
    }
}

// ---------------- distribution epilogue: one warp per batch row ----------------
__global__ void epilogue_kernel(const float* __restrict__ eps,
                                const float* __restrict__ net_in,
                                float* __restrict__ outAction,
                                float* __restrict__ outLogp) {
    const int row  = blockIdx.x * (blockDim.x >> 5) + (threadIdx.x >> 5);
    const int lane = threadIdx.x & 31;
    if (row >= B_ROWS) return;
    const float* net = net_in + (size_t)row * NOUT;
    float s = 0.0f;
    #pragma unroll
    for (int h = 0; h < 2; h++) {
        int j = lane + h*32;
        float mu = net[j];
        float ls = fminf(fmaxf(net[ACT + j], -20.0f), 2.0f);
        float sd = expf(ls);
        float e  = eps[(size_t)row*ACT + j];
        float pi = fmaf(sd, e, mu);
        outAction[(size_t)row*ACT + j] = tanhf(pi);
        float z  = (pi - mu) / sd;
        float m2p = -2.0f * pi;
        float sp  = fmaxf(m2p, 0.0f) + log1pf(expf(-fabsf(m2p)));  // softplus(-2*pi)
        s += -0.5f*z*z - ls - 0.91893853320467274f
             - 2.0f*(0.69314718055994531f - pi - sp);
    }
    #pragma unroll
    for (int o = 16; o; o >>= 1) s += __shfl_xor_sync(0xffffffffu, s, o);
    if (lane == 0 && outLogp) outLogp[row] = s;
}

// ---------------- launcher ----------------
extern "C" void kernel_launch(void* const* d_in, const int* in_sizes, int n_in,
                              void* d_out, int out_size) {
    const float* obs = (const float*)d_in[0];
    const float* eps = (const float*)d_in[1];
    const float* W1  = (const float*)d_in[2];
    const float* b1  = (const float*)d_in[3];
    const float* W2  = (const float*)d_in[4];
    const float* b2  = (const float*)d_in[5];
    const float* W3  = (const float*)d_in[6];
    const float* b3  = (const float*)d_in[7];

    float* out = (float*)d_out;
    float* outAction = out;
    float* outLogp = (out_size >= B_ROWS*(ACT+1)) ? (out + (size_t)B_ROWS*ACT) : nullptr;

    const float S_IN = (float)(1.0/12000.0);

    uint8_t *pW1f, *pW2f, *pW3f, *px, *ph1, *ph2;
    float *pb1q, *pb2q, *pb3q, *pnet;
    cudaGetSymbolAddress((void**)&pW1f, g_W1f);
    cudaGetSymbolAddress((void**)&pW2f, g_W2f);
    cudaGetSymbolAddress((void**)&pW3f, g_W3f);
    cudaGetSymbolAddress((void**)&pb1q, g_b1q);
    cudaGetSymbolAddress((void**)&pb2q, g_b2q);
    cudaGetSymbolAddress((void**)&pb3q, g_b3q);
    cudaGetSymbolAddress((void**)&px,  g_x);
    cudaGetSymbolAddress((void**)&ph1, g_h1);
    cudaGetSymbolAddress((void**)&ph2, g_h2);
    cudaGetSymbolAddress((void**)&pnet, g_net);

    const int SMEM256 = 3 * (ASTG + 256*BK);    // 3*(16K+32K) = 147456
    const int SMEM128 = 3 * (ASTG + 128*BK);    // 3*(16K+16K) =  98304
    cudaFuncSetAttribute(gemm_fp8<256, true>,  cudaFuncAttributeMaxDynamicSharedMemorySize, SMEM256);
    cudaFuncSetAttribute(gemm_fp8<128, false>, cudaFuncAttributeMaxDynamicSharedMemorySize, SMEM128);

    // 1) quantization prep
    zero_max_kernel<<<1, 32>>>();
    maxabs3_kernel<<<416, 256>>>(W1, W2, W3);
    quant_all_kernel<<<512, 256>>>(W1, b1, W2, b2, W3, b3, S_IN);

    // 2) input conversion (fp8)
    conv_x_kernel<<<2048, 256>>>(obs);

    // 3) MLP on tensor cores (fp8 register MMA)
    dim3 g1(H1D/256, B_ROWS/128);
    gemm_fp8<256, true><<<g1, 256, SMEM256>>>(px, pW1f, pb1q, OBS, H1D, 0, ph1, nullptr);
    dim3 g2(H2D/256, B_ROWS/128);
    gemm_fp8<256, true><<<g2, 256, SMEM256>>>(ph1, pW2f, pb2q, H1D, H2D, 1, ph2, nullptr);
    dim3 g3(NOUT/128, B_ROWS/128);
    gemm_fp8<128, false><<<g3, 256, SMEM128>>>(ph2, pW3f, pb3q, H2D, NOUT, 2, nullptr, pnet);

    // 4) squashed-Gaussian epilogue
    epilogue_kernel<<<B_ROWS/8, 256>>>(eps, pnet, outAction, outLogp);
}

// round 8
// speedup vs baseline: 1.0709x; 1.0709x over previous
#include <cuda_runtime.h>
#include <cuda_bf16.h>
#include <math.h>
#include <stdint.h>

#define B_ROWS 32768
#define OBS    512
#define H1D    1024
#define H2D    1024
#define ACT    64
#define NOUT   (2*ACT)

// ---------------- device scratch (static: no allocations allowed) ----------------
__device__ __nv_bfloat16 g_W1r[H1D*OBS];     // integer-valued bf16 weights (exact)
__device__ __nv_bfloat16 g_W2r[H2D*H1D];
__device__ __nv_bfloat16 g_W3r[NOUT*H2D];
__device__ float g_b1q[H1D];
__device__ float g_b2q[H2D];
__device__ float g_b3q[NOUT];
__device__ float g_scales[3];
__device__ unsigned g_maxbits[3];
__device__ __nv_bfloat16 g_x[(size_t)B_ROWS*OBS];
__device__ __nv_bfloat16 g_h1[(size_t)B_ROWS*H1D];
__device__ __nv_bfloat16 g_h2[(size_t)B_ROWS*H2D];

// ---------------- PTX helpers (sm_103-safe subset only) ----------------
__device__ __forceinline__ uint32_t smem_u32(const void* p) {
    uint32_t a;
    asm("{ .reg .u64 t; cvta.to.shared.u64 t, %1; cvt.u32.u64 %0, t; }" : "=r"(a) : "l"(p));
    return a;
}
__device__ __forceinline__ void cpasync16(uint32_t dst, const void* src) {
    asm volatile("cp.async.cg.shared.global [%0], [%1], 16;" :: "r"(dst), "l"(src));
}
__device__ __forceinline__ void cp_commit() { asm volatile("cp.async.commit_group;" ::: "memory"); }
__device__ __forceinline__ void cp_wait2()  { asm volatile("cp.async.wait_group 2;" ::: "memory"); }
__device__ __forceinline__ void cp_wait1()  { asm volatile("cp.async.wait_group 1;" ::: "memory"); }
__device__ __forceinline__ void cp_wait0()  { asm volatile("cp.async.wait_group 0;" ::: "memory"); }

#define LDSM_X4(r0, r1, r2, r3, addr)                                          \
    asm volatile("ldmatrix.sync.aligned.m8n8.x4.shared.b16 {%0,%1,%2,%3}, [%4];" \
        : "=r"(r0), "=r"(r1), "=r"(r2), "=r"(r3) : "r"(addr))

#define MMA16816(c, a0, a1, a2, a3, b0, b1)                                    \
    asm volatile("mma.sync.aligned.m16n8k16.row.col.f32.bf16.bf16.f32 "        \
        "{%0,%1,%2,%3}, {%4,%5,%6,%7}, {%8,%9}, {%0,%1,%2,%3};"                \
        : "+f"((c)[0]), "+f"((c)[1]), "+f"((c)[2]), "+f"((c)[3])               \
        : "r"(a0), "r"(a1), "r"(a2), "r"(a3), "r"(b0), "r"(b1))

// ---------------- quantization prep ----------------
__global__ void zero_max_kernel() {
    if (threadIdx.x < 3) g_maxbits[threadIdx.x] = 0u;
}

// fused 3-tensor max|W|: blocks [0,128)->W1, [128,384)->W2, [384,416)->W3
__global__ void maxabs3_kernel(const float* __restrict__ W1, const float* __restrict__ W2,
                               const float* __restrict__ W3) {
    const float* W; int n, slot, idx, nb;
    int b = blockIdx.x;
    if (b < 128)      { W = W1; n = H1D*OBS;  slot = 0; idx = b;       nb = 128; }
    else if (b < 384) { W = W2; n = H2D*H1D;  slot = 1; idx = b - 128; nb = 256; }
    else              { W = W3; n = NOUT*H2D; slot = 2; idx = b - 384; nb = 32;  }
    unsigned m = 0u;
    for (int i = idx*blockDim.x + threadIdx.x; i < n; i += nb*blockDim.x)
        m = max(m, __float_as_uint(fabsf(W[i])));
    #pragma unroll
    for (int o = 16; o; o >>= 1) m = max(m, __shfl_xor_sync(0xffffffffu, m, o));
    __shared__ unsigned sm[32];
    int lane = threadIdx.x & 31, wid = threadIdx.x >> 5;
    if (lane == 0) sm[wid] = m;
    __syncthreads();
    if (wid == 0) {
        m = (lane < (int)(blockDim.x >> 5)) ? sm[lane] : 0u;
        #pragma unroll
        for (int o = 16; o; o >>= 1) m = max(m, __shfl_xor_sync(0xffffffffu, m, o));
        if (lane == 0) atomicMax(&g_maxbits[slot], m);
    }
}

__device__ __forceinline__ float qwr(float w, float s) {   // integer part only (exact in bf16)
    float r = rintf(__fdiv_rn(w, s));
    return fminf(fmaxf(r, -127.0f), 127.0f);
}
__device__ __forceinline__ float qb(float b, float s) {
    float r = rintf(__fdiv_rn(b, s));
    r = fminf(fmaxf(r, -128.0f), 127.0f);
    return r * s;
}

__global__ void quant_all_kernel(const float* __restrict__ W1, const float* __restrict__ b1,
                                 const float* __restrict__ W2, const float* __restrict__ b2,
                                 const float* __restrict__ W3, const float* __restrict__ b3,
                                 float s_in) {
    const float ws1 = __fdiv_rn(__uint_as_float(g_maxbits[0]), 127.0f);
    const float ws2 = __fdiv_rn(__uint_as_float(g_maxbits[1]), 127.0f);
    const float ws3 = __fdiv_rn(__uint_as_float(g_maxbits[2]), 127.0f);
    const float sb1 = s_in * ws1;
    const float sb2 = sb1 * ws2;
    const float sb3 = sb2 * ws3;
    const int tid = blockIdx.x*blockDim.x + threadIdx.x;
    const int stride = gridDim.x*blockDim.x;
    if (tid == 0) { g_scales[0] = ws1; g_scales[1] = ws2; g_scales[2] = ws3; }
    for (int i = tid; i < H1D*OBS;  i += stride) g_W1r[i] = __float2bfloat16(qwr(W1[i], ws1));
    for (int i = tid; i < H2D*H1D;  i += stride) g_W2r[i] = __float2bfloat16(qwr(W2[i], ws2));
    for (int i = tid; i < NOUT*H2D; i += stride) g_W3r[i] = __float2bfloat16(qwr(W3[i], ws3));
    for (int i = tid; i < H1D;  i += stride) g_b1q[i] = qb(b1[i], sb1);
    for (int i = tid; i < H2D;  i += stride) g_b2q[i] = qb(b2[i], sb2);
    for (int i = tid; i < NOUT; i += stride) g_b3q[i] = qb(b3[i], sb3);
}

// ---------------- input conversion: x = obs * s_in^2 as bf16 ----------------
__global__ void conv_x_kernel(const float* __restrict__ obs) {
    const float F0 = (float)((1.0/12000.0) * (1.0/12000.0));
    const size_t n2 = (size_t)B_ROWS * OBS / 2;
    for (size_t i = (size_t)blockIdx.x*blockDim.x + threadIdx.x; i < n2;
         i += (size_t)gridDim.x*blockDim.x) {
        float2 v = ((const float2*)obs)[i];
        __nv_bfloat162 p;
        p.x = __float2bfloat16(v.x * F0);
        p.y = __float2bfloat16(v.y * F0);
        ((__nv_bfloat162*)g_x)[i] = p;
    }
}

// ---------------- HMMA GEMM, 512 threads (16 warps, 4Mx4N), warp tile 32 x NTILE/4 ----------------
// D[128,NTILE] per CTA = A[M,K] @ Wr[N,K]^T. K in BK=64 chunks, 3-stage cp.async ring.
// FUSED=false: epilogue *ws + bias + relu -> bf16 oH.
// FUSED=true (layer 3, NTILE=128=NOUT): stage net rows in smem, compute squashed-
//   Gaussian action + logp directly (no g_net round-trip).
#define BK 64
#define ASTG (128*BK*2)          // 16 KB A per stage

template<int NTILE, bool FUSED>
__global__ __launch_bounds__(512, 1)
void gemm_mma(const __nv_bfloat16* __restrict__ A,
              const __nv_bfloat16* __restrict__ Br,  const float* __restrict__ bias,
              int K, int Nd, int sIdx,
              __nv_bfloat16* __restrict__ oH,
              const float* __restrict__ eps,
              float* __restrict__ outAction, float* __restrict__ outLogp) {
    constexpr int BSTG = NTILE * 128;           // B bytes per stage
    constexpr int STG  = ASTG + BSTG;
    constexpr int NT   = NTILE / 32;            // n-subtiles per warp (8 or 4)
    extern __shared__ __align__(128) char smem[];
    const uint32_t sb = smem_u32(smem);
    const int tid = threadIdx.x, wid = tid >> 5, lane = tid & 31;
    const int bm = blockIdx.y * 128, bn = blockIdx.x * NTILE;
    const int wm = wid >> 2, wn = wid & 3;      // 4 x 4 warps

    float acc[2][NT][4];
    #pragma unroll
    for (int i = 0; i < 2; i++)
        #pragma unroll
        for (int j = 0; j < NT; j++)
            #pragma unroll
            for (int v = 0; v < 4; v++) acc[i][j][v] = 0.0f;

    const int nIter = K >> 6;

    auto load_stage = [&](int i) {
        const uint32_t s0 = sb + (i % 3) * STG;
        const int k0 = i << 6;
        #pragma unroll
        for (int o = 0; o < 2; o++) {                   // A: 128 rows x 8 chunks
            int idx = tid + o * 512;
            int r = idx >> 3, c = idx & 7;
            uint32_t soff = (uint32_t)(r * 128 + ((c ^ (r & 7)) << 4));
            cpasync16(s0 + soff, A + (size_t)(bm + r) * K + k0 + c * 8);
        }
        #pragma unroll
        for (int o = 0; o < NTILE / 64; o++) {          // B: NTILE rows x 8 chunks
            int idx = tid + o * 512;
            int r = idx >> 3, c = idx & 7;
            cpasync16(s0 + ASTG + (uint32_t)(r * 128 + ((c ^ (r & 7)) << 4)),
                      Br + (size_t)(bn + r) * K + k0 + c * 8);
        }
        cp_commit();
    };

    // per-thread ldmatrix row/group decomposition (validated layout)
    const int g  = lane >> 3;
    const int glr = lane & 7;
    const int arow = (g & 1) * 8 + glr;   // A x4: rows pair then chunk pair
    const int ach  = g >> 1;
    const int brow = (g >> 1) * 8 + glr;  // B x4: chunk pair then rows pair
    const int bch  = g & 1;

    load_stage(0);
    if (nIter > 1) load_stage(1);

    for (int i = 0; i < nIter; ++i) {
        if (i + 2 < nIter)      { load_stage(i + 2); cp_wait2(); }
        else if (i + 1 < nIter) { cp_wait1(); }
        else                    { cp_wait0(); }
        __syncthreads();

        const uint32_t s0 = sb + (i % 3) * STG;
        #pragma unroll
        for (int ks = 0; ks < 4; ks++) {
            const int c0 = ks * 2;
            uint32_t bf[NT][2];
            #pragma unroll
            for (int nt2 = 0; nt2 < NT / 2; nt2++) {
                int row = wn * (NTILE / 4) + nt2 * 16 + brow;
                uint32_t addr = s0 + ASTG + row * 128 + (((c0 + bch) ^ (row & 7)) << 4);
                LDSM_X4(bf[2*nt2][0], bf[2*nt2][1], bf[2*nt2+1][0], bf[2*nt2+1][1], addr);
            }
            uint32_t af[2][4];
            #pragma unroll
            for (int mt = 0; mt < 2; mt++) {
                int row = wm * 32 + mt * 16 + arow;
                uint32_t addr = s0 + row * 128 + (((c0 + ach) ^ (row & 7)) << 4);
                LDSM_X4(af[mt][0], af[mt][1], af[mt][2], af[mt][3], addr);
            }
            #pragma unroll
            for (int mt = 0; mt < 2; mt++)
                #pragma unroll
                for (int nt = 0; nt < NT; nt++)
                    MMA16816(acc[mt][nt], af[mt][0], af[mt][1], af[mt][2], af[mt][3],
                             bf[nt][0], bf[nt][1]);
        }
        __syncthreads();
    }

    // ---- epilogue ----
    const float ws = g_scales[sIdx];
    const int qr = lane >> 2;
    const int qc = (lane & 3) * 2;

    if (!FUSED) {
        #pragma unroll
        for (int mt = 0; mt < 2; mt++) {
            #pragma unroll
            for (int nt = 0; nt < NT; nt++) {
                int col = bn + wn * (NTILE / 4) + nt * 8 + qc;
                float bs0 = __ldg(&bias[col]), bs1 = __ldg(&bias[col + 1]);
                #pragma unroll
                for (int h = 0; h < 2; h++) {
                    size_t row = (size_t)(bm + wm * 32 + mt * 16 + qr + h * 8);
                    float o0 = fmaf(acc[mt][nt][2*h + 0], ws, bs0);
                    float o1 = fmaf(acc[mt][nt][2*h + 1], ws, bs1);
                    __nv_bfloat162 p;
                    p.x = __float2bfloat16(fmaxf(o0, 0.0f));
                    p.y = __float2bfloat16(fmaxf(o1, 0.0f));
                    *reinterpret_cast<__nv_bfloat162*>(oH + row * Nd + col) = p;
                }
            }
        }
    } else {
        // stage scaled net rows into smem: snet[128][128]  (64 KB, reuses pipeline smem)
        float* snet = reinterpret_cast<float*>(smem);
        #pragma unroll
        for (int mt = 0; mt < 2; mt++) {
            #pragma unroll
            for (int nt = 0; nt < NT; nt++) {
                int col = wn * (NTILE / 4) + nt * 8 + qc;
                float bs0 = __ldg(&bias[col]), bs1 = __ldg(&bias[col + 1]);
                #pragma unroll
                for (int h = 0; h < 2; h++) {
                    int row = wm * 32 + mt * 16 + qr + h * 8;
                    snet[row * 128 + col]     = fmaf(acc[mt][nt][2*h + 0], ws, bs0);
                    snet[row * 128 + col + 1] = fmaf(acc[mt][nt][2*h + 1], ws, bs1);
                }
            }
        }
        __syncthreads();
        // distribution: each of 16 warps handles 8 rows
        #pragma unroll
        for (int rr = 0; rr < 8; rr++) {
            int row = wid * 8 + rr;
            size_t grow = (size_t)(bm + row);
            float s = 0.0f;
            #pragma unroll
            for (int h = 0; h < 2; h++) {
                int j = lane + h * 32;
                float mu = snet[row * 128 + j];
                float ls = fminf(fmaxf(snet[row * 128 + ACT + j], -20.0f), 2.0f);
                float sd = expf(ls);
                float e  = eps[grow * ACT + j];
                float pi = fmaf(sd, e, mu);
                outAction[grow * ACT + j] = tanhf(pi);
                float z  = (pi - mu) / sd;
                float m2p = -2.0f * pi;
                float sp  = fmaxf(m2p, 0.0f) + log1pf(expf(-fabsf(m2p)));  // softplus(-2*pi)
                s += -0.5f*z*z - ls - 0.91893853320467274f
                     - 2.0f*(0.69314718055994531f - pi - sp);
            }
            #pragma unroll
            for (int o = 16; o; o >>= 1) s += __shfl_xor_sync(0xffffffffu, s, o);
            if (lane == 0 && outLogp) outLogp[grow] = s;
        }
    }
}

// ---------------- launcher ----------------
extern "C" void kernel_launch(void* const* d_in, const int* in_sizes, int n_in,
                              void* d_out, int out_size) {
    const float* obs = (const float*)d_in[0];
    const float* eps = (const float*)d_in[1];
    const float* W1  = (const float*)d_in[2];
    const float* b1  = (const float*)d_in[3];
    const float* W2  = (const float*)d_in[4];
    const float* b2  = (const float*)d_in[5];
    const float* W3  = (const float*)d_in[6];
    const float* b3  = (const float*)d_in[7];

    float* out = (float*)d_out;
    float* outAction = out;
    float* outLogp = (out_size >= B_ROWS*(ACT+1)) ? (out + (size_t)B_ROWS*ACT) : nullptr;

    const float S_IN = (float)(1.0/12000.0);

    __nv_bfloat16 *pW1r, *pW2r, *pW3r, *px, *ph1, *ph2;
    float *pb1q, *pb2q, *pb3q;
    cudaGetSymbolAddress((void**)&pW1r, g_W1r);
    cudaGetSymbolAddress((void**)&pW2r, g_W2r);
    cudaGetSymbolAddress((void**)&pW3r, g_W3r);
    cudaGetSymbolAddress((void**)&pb1q, g_b1q);
    cudaGetSymbolAddress((void**)&pb2q, g_b2q);
    cudaGetSymbolAddress((void**)&pb3q, g_b3q);
    cudaGetSymbolAddress((void**)&px,  g_x);
    cudaGetSymbolAddress((void**)&ph1, g_h1);
    cudaGetSymbolAddress((void**)&ph2, g_h2);

    const int SMEM256 = 3 * (ASTG + 256*128);   // 147456
    const int SMEM128 = 3 * (ASTG + 128*128);   //  98304 (>= 64KB snet)
    cudaFuncSetAttribute(gemm_mma<256, false>, cudaFuncAttributeMaxDynamicSharedMemorySize, SMEM256);
    cudaFuncSetAttribute(gemm_mma<128, true>,  cudaFuncAttributeMaxDynamicSharedMemorySize, SMEM128);

    // 1) quantization prep
    zero_max_kernel<<<1, 32>>>();
    maxabs3_kernel<<<416, 256>>>(W1, W2, W3);
    quant_all_kernel<<<512, 256>>>(W1, b1, W2, b2, W3, b3, S_IN);

    // 2) input conversion
    conv_x_kernel<<<2048, 256>>>(obs);

    // 3) MLP on tensor cores (register HMMA, 16 warps/CTA)
    dim3 g1(H1D/256, B_ROWS/128);
    gemm_mma<256, false><<<g1, 512, SMEM256>>>(px, pW1r, pb1q, OBS, H1D, 0, ph1,
                                               nullptr, nullptr, nullptr);
    dim3 g2(H2D/256, B_ROWS/128);
    gemm_mma<256, false><<<g2, 512, SMEM256>>>(ph1, pW2r, pb2q, H1D, H2D, 1, ph2,
                                               nullptr, nullptr, nullptr);
    dim3 g3(1, B_ROWS/128);
    gemm_mma<128, true><<<g3, 512, SMEM128>>>(ph2, pW3r, pb3q, H2D, NOUT, 2, nullptr,
                                              eps, outAction, outLogp);
}